// round 4
// baseline (speedup 1.0000x reference)
#include <cuda_runtime.h>
#include <math.h>

// Problem constants
#define NBATCH 8
#define CCH    256
#define TSEQ   1024
#define NHEAD  8
#define HDIM   32

typedef unsigned long long u64;

// ---- packed f32x2 primitives (sm_100+) ----
__device__ __forceinline__ u64 bcast2(float x) {
    u64 r; asm("mov.b64 %0, {%1, %1};" : "=l"(r) : "f"(x)); return r;
}
__device__ __forceinline__ u64 fma2(u64 a, u64 b, u64 c) {
    u64 d; asm("fma.rn.f32x2 %0, %1, %2, %3;" : "=l"(d) : "l"(a), "l"(b), "l"(c));
    return d;
}
__device__ __forceinline__ u64 add2(u64 a, u64 b) {
    u64 d; asm("add.rn.f32x2 %0, %1, %2;" : "=l"(d) : "l"(a), "l"(b)); return d;
}
__device__ __forceinline__ float2 unpk2(u64 a) {
    float2 f; asm("mov.b64 {%0, %1}, %2;" : "=f"(f.x), "=f"(f.y) : "l"(a)); return f;
}

// Scratch. K/Q/V in [N, H, T, D]. g_attn TRANSPOSED: [C, N*T].
__device__ float g_k[NBATCH * NHEAD * TSEQ * HDIM];
__device__ float g_q[NBATCH * NHEAD * TSEQ * HDIM];
__device__ float g_v[NBATCH * NHEAD * TSEQ * HDIM];
__device__ float g_attn[CCH * NBATCH * TSEQ];

// ---------------------------------------------------------------------------
// Kernel 1: KQV projection, f32x2.  A[m,k] = image[n, k, t]  (m = n*1024 + t)
// B = w_kqv [256, 768]. 128x128 tile, BK=16, 256 threads, 8x8 micro-tile.
// B stored duplicated in shared so packed broadcasts load directly.
// ---------------------------------------------------------------------------
__global__ __launch_bounds__(256) void kqv_gemm(const float* __restrict__ image,
                                                const float* __restrict__ w,
                                                const float* __restrict__ bias) {
    __shared__ float As[16][128];
    __shared__ float Bs[16][256];   // duplicated pairs: Bs[kk][2c]=Bs[kk][2c+1]=B[kk][c]
    const int bm = blockIdx.y * 128;
    const int bn = blockIdx.x * 128;
    const int tid = threadIdx.x;
    const int tx = tid & 15;        // m: 16 threads x 8 rows
    const int ty = tid >> 4;        // n: 16 threads x 8 cols
    const int n  = bm >> 10;
    const int t0 = bm & 1023;

    u64 acc[4][8];
    #pragma unroll
    for (int i = 0; i < 4; i++)
        #pragma unroll
        for (int j = 0; j < 8; j++) acc[i][j] = 0ull;

    for (int k0 = 0; k0 < 256; k0 += 16) {
        #pragma unroll
        for (int l = 0; l < 2; l++) {
            int idx = l * 256 + tid;            // 512 float4: 16 rows x 32
            int kk = idx >> 5, f4 = idx & 31;
            *(float4*)&As[kk][f4 * 4] =
                *(const float4*)&image[n * 262144 + (k0 + kk) * 1024 + t0 + f4 * 4];
            float4 b = *(const float4*)&w[(k0 + kk) * 768 + bn + f4 * 4];
            *(float4*)&Bs[kk][f4 * 8]     = make_float4(b.x, b.x, b.y, b.y);
            *(float4*)&Bs[kk][f4 * 8 + 4] = make_float4(b.z, b.z, b.w, b.w);
        }
        __syncthreads();
        #pragma unroll
        for (int kk = 0; kk < 16; kk++) {
            const u64* ap = (const u64*)&As[kk][tx * 8];
            const u64* bp = (const u64*)&Bs[kk][ty * 16];
            u64 a2[4], b2[8];
            #pragma unroll
            for (int i = 0; i < 4; i++) a2[i] = ap[i];
            #pragma unroll
            for (int j = 0; j < 8; j++) b2[j] = bp[j];
            #pragma unroll
            for (int i = 0; i < 4; i++)
                #pragma unroll
                for (int j = 0; j < 8; j++)
                    acc[i][j] = fma2(a2[i], b2[j], acc[i][j]);
        }
        __syncthreads();
    }

    // Epilogue: thread owns 8 consecutive o (single 'which', single head).
    const int o0 = bn + ty * 8;
    const int which = o0 >> 8;
    const int c = o0 & 255;
    const int h = c >> 5;
    const int d0 = c & 31;
    float* dst = (which == 0) ? g_k : (which == 1) ? g_q : g_v;
    float bv[8];
    *(float4*)&bv[0] = *(const float4*)&bias[o0];
    *(float4*)&bv[4] = *(const float4*)&bias[o0 + 4];

    #pragma unroll
    for (int i2 = 0; i2 < 4; i2++) {
        float2 p[8];
        #pragma unroll
        for (int j = 0; j < 8; j++) p[j] = unpk2(acc[i2][j]);
        const int t = t0 + tx * 8 + 2 * i2;
        const size_t base = ((size_t)(n * NHEAD + h) * TSEQ + t) * HDIM + d0;
        *(float4*)&dst[base] = make_float4(p[0].x + bv[0], p[1].x + bv[1],
                                           p[2].x + bv[2], p[3].x + bv[3]);
        *(float4*)&dst[base + 4] = make_float4(p[4].x + bv[4], p[5].x + bv[5],
                                               p[6].x + bv[6], p[7].x + bv[7]);
        *(float4*)&dst[base + HDIM] = make_float4(p[0].y + bv[0], p[1].y + bv[1],
                                                  p[2].y + bv[2], p[3].y + bv[3]);
        *(float4*)&dst[base + HDIM + 4] = make_float4(p[4].y + bv[4], p[5].y + bv[5],
                                                      p[6].y + bv[6], p[7].y + bv[7]);
    }
}

// ---------------------------------------------------------------------------
// Kernel 2: causal flash attention, f32x2. 1 thread = 1 query row.
// ---------------------------------------------------------------------------
__global__ __launch_bounds__(128) void attn_kernel() {
    const int qt = (int)gridDim.x - 1 - (int)blockIdx.x;  // heavy tiles first
    const int nh = blockIdx.y;
    const int tid = threadIdx.x;
    const int tq = qt * 128 + tid;

    const float* Qb = g_q + (size_t)nh * TSEQ * HDIM;
    const float* Kb = g_k + (size_t)nh * TSEQ * HDIM;
    const float* Vb = g_v + (size_t)nh * TSEQ * HDIM;

    u64 q2[16];
    {
        const u64* qsrc = (const u64*)(Qb + (size_t)tq * HDIM);
        #pragma unroll
        for (int d2 = 0; d2 < 16; d2++) q2[d2] = qsrc[d2];
    }

    u64 acc[16];
    #pragma unroll
    for (int d2 = 0; d2 < 16; d2++) acc[d2] = 0ull;
    float mmax = -INFINITY;
    float lsum = 0.0f;

    __shared__ float Ks[64 * 32];
    __shared__ float Vs[64 * 32];

    const float scale = 0.17677669529663687f;  // 1/sqrt(32)
    const int full_tiles = qt * 2;
    const int ntiles = full_tiles + 2;

    for (int kt = 0; kt < ntiles; kt++) {
        __syncthreads();
        {
            const float4* ksrc = (const float4*)(Kb + (size_t)kt * 64 * HDIM);
            const float4* vsrc = (const float4*)(Vb + (size_t)kt * 64 * HDIM);
            #pragma unroll
            for (int l = 0; l < 4; l++) {
                ((float4*)Ks)[l * 128 + tid] = ksrc[l * 128 + tid];
                ((float4*)Vs)[l * 128 + tid] = vsrc[l * 128 + tid];
            }
        }
        __syncthreads();

        const bool full = (kt < full_tiles);
        const int base = kt * 64;
        const int jmax = full ? 64 : (tq - base + 1 < 64 ? tq - base + 1 : 64);

        #pragma unroll 2
        for (int j = 0; j < jmax; j++) {
            const u64* kp = (const u64*)&Ks[j * 32];
            u64 s0 = 0ull, s1 = 0ull, s2 = 0ull, s3 = 0ull;
            #pragma unroll
            for (int d2 = 0; d2 < 16; d2 += 4) {
                s0 = fma2(q2[d2 + 0], kp[d2 + 0], s0);
                s1 = fma2(q2[d2 + 1], kp[d2 + 1], s1);
                s2 = fma2(q2[d2 + 2], kp[d2 + 2], s2);
                s3 = fma2(q2[d2 + 3], kp[d2 + 3], s3);
            }
            float2 sf = unpk2(add2(add2(s0, s1), add2(s2, s3)));
            const float s = (sf.x + sf.y) * scale;

            const u64* vp = (const u64*)&Vs[j * 32];
            if (s <= mmax) {
                float p = __expf(s - mmax);
                lsum += p;
                u64 pd = bcast2(p);
                #pragma unroll
                for (int d2 = 0; d2 < 16; d2++)
                    acc[d2] = fma2(pd, vp[d2], acc[d2]);
            } else {
                float r = __expf(mmax - s);   // exp(-inf)=0 bootstraps cleanly
                mmax = s;
                lsum = lsum * r + 1.0f;
                u64 rd = bcast2(r);
                #pragma unroll
                for (int d2 = 0; d2 < 16; d2++)
                    acc[d2] = fma2(acc[d2], rd, vp[d2]);
            }
        }
    }

    // Write to g_attn [C, N*T]: scalar stores, lane-contiguous (coalesced).
    const float inv = 1.0f / lsum;
    const int n = nh >> 3;
    const int h = nh & 7;
    const size_t mcol = (size_t)n * TSEQ + tq;
    #pragma unroll
    for (int d2 = 0; d2 < 16; d2++) {
        float2 f = unpk2(acc[d2]);
        g_attn[(size_t)(h * HDIM + 2 * d2 + 0) * (NBATCH * TSEQ) + mcol] = f.x * inv;
        g_attn[(size_t)(h * HDIM + 2 * d2 + 1) * (NBATCH * TSEQ) + mcol] = f.y * inv;
    }
}

// ---------------------------------------------------------------------------
// Kernel 3: mix + bias + residual, f32x2 -> out [N, C, H*W].
//   A[m,k] = g_attn[k, m]. 128x64 tile, BK=16, 256 threads, 8x4 micro.
// ---------------------------------------------------------------------------
__global__ __launch_bounds__(256) void mix_gemm(const float* __restrict__ image,
                                                const float* __restrict__ w,
                                                const float* __restrict__ bias,
                                                float* __restrict__ out) {
    __shared__ float As[16][128];
    __shared__ float Bs[16][128];   // duplicated pairs
    const int bm = blockIdx.y * 128;
    const int bn = blockIdx.x * 64;
    const int tid = threadIdx.x;
    const int tx = tid & 15;        // m: 16 x 8
    const int ty = tid >> 4;        // n: 16 x 4
    const int n  = bm >> 10;
    const int t0 = bm & 1023;

    u64 acc[4][4];
    #pragma unroll
    for (int i = 0; i < 4; i++)
        #pragma unroll
        for (int j = 0; j < 4; j++) acc[i][j] = 0ull;

    for (int k0 = 0; k0 < 256; k0 += 16) {
        #pragma unroll
        for (int l = 0; l < 2; l++) {
            int idx = l * 256 + tid;
            int kk = idx >> 5, f4 = idx & 31;
            *(float4*)&As[kk][f4 * 4] =
                *(const float4*)&g_attn[(size_t)(k0 + kk) * 8192 + bm + f4 * 4];
        }
        {
            int kk = tid >> 4, f4 = tid & 15;   // 256 float4 = 16 rows x 16
            float4 b = *(const float4*)&w[(k0 + kk) * 256 + bn + f4 * 4];
            *(float4*)&Bs[kk][f4 * 8]     = make_float4(b.x, b.x, b.y, b.y);
            *(float4*)&Bs[kk][f4 * 8 + 4] = make_float4(b.z, b.z, b.w, b.w);
        }
        __syncthreads();
        #pragma unroll
        for (int kk = 0; kk < 16; kk++) {
            const u64* ap = (const u64*)&As[kk][tx * 8];
            const u64* bp = (const u64*)&Bs[kk][ty * 8];
            u64 a2[4], b2[4];
            #pragma unroll
            for (int i = 0; i < 4; i++) a2[i] = ap[i];
            #pragma unroll
            for (int j = 0; j < 4; j++) b2[j] = bp[j];
            #pragma unroll
            for (int i = 0; i < 4; i++)
                #pragma unroll
                for (int j = 0; j < 4; j++)
                    acc[i][j] = fma2(a2[i], b2[j], acc[i][j]);
        }
        __syncthreads();
    }

    // Epilogue: for each of 4 o, 8 consecutive t per thread -> 2 float4 stores.
    #pragma unroll
    for (int j = 0; j < 4; j++) {
        const int o = bn + ty * 4 + j;
        const float bo = bias[o];
        float2 p0 = unpk2(acc[0][j]), p1 = unpk2(acc[1][j]);
        float2 p2 = unpk2(acc[2][j]), p3 = unpk2(acc[3][j]);
        const size_t gbase = (size_t)n * 262144 + (size_t)o * 1024 + t0 + tx * 8;
        float4 i0 = *(const float4*)&image[gbase];
        float4 i1 = *(const float4*)&image[gbase + 4];
        *(float4*)&out[gbase] = make_float4(p0.x + bo + i0.x, p0.y + bo + i0.y,
                                            p1.x + bo + i0.z, p1.y + bo + i0.w);
        *(float4*)&out[gbase + 4] = make_float4(p2.x + bo + i1.x, p2.y + bo + i1.y,
                                                p3.x + bo + i1.z, p3.y + bo + i1.w);
    }
}

// ---------------------------------------------------------------------------
extern "C" void kernel_launch(void* const* d_in, const int* in_sizes, int n_in,
                              void* d_out, int out_size) {
    const float* image = (const float*)d_in[0];
    const float* w_kqv = (const float*)d_in[1];
    const float* b_kqv = (const float*)d_in[2];
    const float* w_mix = (const float*)d_in[3];
    const float* b_mix = (const float*)d_in[4];
    float* out = (float*)d_out;

    dim3 gridA(768 / 128, 8192 / 128);
    kqv_gemm<<<gridA, 256>>>(image, w_kqv, b_kqv);

    dim3 gridB(8, 64);
    attn_kernel<<<gridB, 128>>>();

    dim3 gridC(256 / 64, 8192 / 128);
    mix_gemm<<<gridC, 256>>>(image, w_mix, b_mix, out);
}

// round 5
// speedup vs baseline: 1.5231x; 1.5231x over previous
#include <cuda_runtime.h>
#include <math.h>

// Problem constants
#define NBATCH 8
#define CCH    256
#define TSEQ   1024
#define NHEAD  8
#define HDIM   32

typedef unsigned long long u64;

// ---- packed f32x2 primitives (sm_100+) ----
__device__ __forceinline__ u64 bcast2(float x) {
    u64 r; asm("mov.b64 %0, {%1, %1};" : "=l"(r) : "f"(x)); return r;
}
__device__ __forceinline__ u64 fma2(u64 a, u64 b, u64 c) {
    u64 d; asm("fma.rn.f32x2 %0, %1, %2, %3;" : "=l"(d) : "l"(a), "l"(b), "l"(c));
    return d;
}
__device__ __forceinline__ u64 mul2(u64 a, u64 b) {
    u64 d; asm("mul.rn.f32x2 %0, %1, %2;" : "=l"(d) : "l"(a), "l"(b)); return d;
}
__device__ __forceinline__ u64 add2(u64 a, u64 b) {
    u64 d; asm("add.rn.f32x2 %0, %1, %2;" : "=l"(d) : "l"(a), "l"(b)); return d;
}
__device__ __forceinline__ float2 unpk2(u64 a) {
    float2 f; asm("mov.b64 {%0, %1}, %2;" : "=f"(f.x), "=f"(f.y) : "l"(a)); return f;
}

// Scratch. K/Q/V in [N, H, T, D]. g_attn TRANSPOSED: [C, N*T].
__device__ float g_k[NBATCH * NHEAD * TSEQ * HDIM];
__device__ float g_q[NBATCH * NHEAD * TSEQ * HDIM];
__device__ float g_v[NBATCH * NHEAD * TSEQ * HDIM];
__device__ float g_attn[CCH * NBATCH * TSEQ];

// ---------------------------------------------------------------------------
// Kernel 1: KQV projection (R3-proven).  A[m,k] = image[n, k, t]
// B = w_kqv [256, 768]. 64x64 tile, BK=32, 256 threads, 4x4 micro-tile.
// ---------------------------------------------------------------------------
__global__ __launch_bounds__(256) void kqv_gemm(const float* __restrict__ image,
                                                const float* __restrict__ w,
                                                const float* __restrict__ bias) {
    __shared__ float As[32][64];
    __shared__ float Bs[32][64];
    const int bm = blockIdx.y * 64;
    const int bn = blockIdx.x * 64;
    const int tid = threadIdx.x;
    const int tx = tid & 15;
    const int ty = tid >> 4;
    const int n  = bm >> 10;
    const int t0 = bm & 1023;

    float acc[4][4] = {};
    float4* As4 = (float4*)&As[0][0];
    float4* Bs4 = (float4*)&Bs[0][0];

    for (int k0 = 0; k0 < 256; k0 += 32) {
        #pragma unroll
        for (int l = 0; l < 2; l++) {
            int idx = l * 256 + tid;
            int kk = idx >> 4, f4 = idx & 15;
            As4[idx] = *(const float4*)&image[n * 262144 + (k0 + kk) * 1024 + t0 + f4 * 4];
            Bs4[idx] = *(const float4*)&w[(k0 + kk) * 768 + bn + f4 * 4];
        }
        __syncthreads();
        #pragma unroll
        for (int kk = 0; kk < 32; kk++) {
            float4 a = *(const float4*)&As[kk][tx * 4];
            float4 b = *(const float4*)&Bs[kk][ty * 4];
            acc[0][0] += a.x * b.x; acc[0][1] += a.x * b.y; acc[0][2] += a.x * b.z; acc[0][3] += a.x * b.w;
            acc[1][0] += a.y * b.x; acc[1][1] += a.y * b.y; acc[1][2] += a.y * b.z; acc[1][3] += a.y * b.w;
            acc[2][0] += a.z * b.x; acc[2][1] += a.z * b.y; acc[2][2] += a.z * b.z; acc[2][3] += a.z * b.w;
            acc[3][0] += a.w * b.x; acc[3][1] += a.w * b.y; acc[3][2] += a.w * b.z; acc[3][3] += a.w * b.w;
        }
        __syncthreads();
    }

    const int o0 = bn + ty * 4;
    const int which = o0 >> 8;
    const int c = o0 & 255;
    const int h = c >> 5;
    const int d0 = c & 31;
    float* dst = (which == 0) ? g_k : (which == 1) ? g_q : g_v;
    const float4 b4 = *(const float4*)&bias[o0];
    #pragma unroll
    for (int i = 0; i < 4; i++) {
        const int t = t0 + tx * 4 + i;
        float4 v = make_float4(acc[i][0] + b4.x, acc[i][1] + b4.y,
                               acc[i][2] + b4.z, acc[i][3] + b4.w);
        *(float4*)&dst[((size_t)(n * NHEAD + h) * TSEQ + t) * HDIM + d0] = v;
    }
}

// ---------------------------------------------------------------------------
// Kernel 2: causal flash attention, BRANCHLESS chunked online softmax + f32x2.
// 1 thread = 1 query row, 128 q/block. Chunks of 16 keys: one rescale/chunk.
// ---------------------------------------------------------------------------
__global__ __launch_bounds__(128) void attn_kernel() {
    const int qt = 7 - (int)blockIdx.x;  // heavy tiles first
    const int nh = blockIdx.y;
    const int tid = threadIdx.x;
    const int tq = qt * 128 + tid;

    const float* Qb = g_q + (size_t)nh * TSEQ * HDIM;
    const float* Kb = g_k + (size_t)nh * TSEQ * HDIM;
    const float* Vb = g_v + (size_t)nh * TSEQ * HDIM;

    // Q row pre-scaled by 1/sqrt(D)
    u64 q2[16];
    {
        const u64 sc2 = bcast2(0.17677669529663687f);
        const u64* qsrc = (const u64*)(Qb + (size_t)tq * HDIM);
        #pragma unroll
        for (int d2 = 0; d2 < 16; d2++) q2[d2] = mul2(qsrc[d2], sc2);
    }

    u64 acc[16];
    #pragma unroll
    for (int d2 = 0; d2 < 16; d2++) acc[d2] = 0ull;
    float mmax = -1e30f;
    float lsum = 0.0f;

    __shared__ float Ks[64 * 32];
    __shared__ float Vs[64 * 32];

    const int full_tiles = qt * 2;
    const int ntiles = full_tiles + 2;

    for (int kt = 0; kt < ntiles; kt++) {
        __syncthreads();
        {
            const float4* ksrc = (const float4*)(Kb + (size_t)kt * 64 * HDIM);
            const float4* vsrc = (const float4*)(Vb + (size_t)kt * 64 * HDIM);
            #pragma unroll
            for (int l = 0; l < 4; l++) {
                ((float4*)Ks)[l * 128 + tid] = ksrc[l * 128 + tid];
                ((float4*)Vs)[l * 128 + tid] = vsrc[l * 128 + tid];
            }
        }
        __syncthreads();

        const bool full = (kt < full_tiles);
        const int base = kt * 64;

        for (int c = 0; c < 4; c++) {               // 4 chunks of 16 keys
            float sc[16];
            // --- scores for the chunk (branchless causal mask via SEL) ---
            #pragma unroll
            for (int j = 0; j < 16; j++) {
                const int key = c * 16 + j;
                const u64* kp = (const u64*)&Ks[key * 32];
                u64 s0 = 0ull, s1 = 0ull, s2 = 0ull, s3 = 0ull;
                #pragma unroll
                for (int d2 = 0; d2 < 16; d2 += 4) {
                    s0 = fma2(q2[d2 + 0], kp[d2 + 0], s0);
                    s1 = fma2(q2[d2 + 1], kp[d2 + 1], s1);
                    s2 = fma2(q2[d2 + 2], kp[d2 + 2], s2);
                    s3 = fma2(q2[d2 + 3], kp[d2 + 3], s3);
                }
                float2 sf = unpk2(add2(add2(s0, s1), add2(s2, s3)));
                float s = sf.x + sf.y;
                if (!full) s = (base + key <= tq) ? s : -1e30f;   // SEL, no branch
                sc[j] = s;
            }
            // --- chunk max (tree) ---
            float cm01 = fmaxf(fmaxf(sc[0], sc[1]), fmaxf(sc[2], sc[3]));
            float cm23 = fmaxf(fmaxf(sc[4], sc[5]), fmaxf(sc[6], sc[7]));
            float cm45 = fmaxf(fmaxf(sc[8], sc[9]), fmaxf(sc[10], sc[11]));
            float cm67 = fmaxf(fmaxf(sc[12], sc[13]), fmaxf(sc[14], sc[15]));
            const float cmax = fmaxf(fmaxf(cm01, cm23), fmaxf(cm45, cm67));
            const float mnew = fmaxf(mmax, cmax);
            const float r = __expf(mmax - mnew);    // ==1 if no new max; ==0 on bootstrap
            mmax = mnew;
            lsum *= r;
            const u64 rd = bcast2(r);
            #pragma unroll
            for (int d2 = 0; d2 < 16; d2++) acc[d2] = mul2(acc[d2], rd);
            // --- accumulate (straight-line) ---
            #pragma unroll
            for (int j = 0; j < 16; j++) {
                const float p = __expf(sc[j] - mnew);
                lsum += p;
                const u64 pd = bcast2(p);
                const u64* vp = (const u64*)&Vs[(c * 16 + j) * 32];
                #pragma unroll
                for (int d2 = 0; d2 < 16; d2++)
                    acc[d2] = fma2(pd, vp[d2], acc[d2]);
            }
        }
    }

    // Write to g_attn [C, N*T]: scalar stores, lane-contiguous (coalesced).
    const float inv = 1.0f / lsum;
    const int n = nh >> 3;
    const int h = nh & 7;
    const size_t mcol = (size_t)n * TSEQ + tq;
    #pragma unroll
    for (int d2 = 0; d2 < 16; d2++) {
        float2 f = unpk2(acc[d2]);
        g_attn[(size_t)(h * HDIM + 2 * d2 + 0) * (NBATCH * TSEQ) + mcol] = f.x * inv;
        g_attn[(size_t)(h * HDIM + 2 * d2 + 1) * (NBATCH * TSEQ) + mcol] = f.y * inv;
    }
}

// ---------------------------------------------------------------------------
// Kernel 3: mix + bias + residual (R3-proven) -> out [N, C, H*W].
//   A[m,k] = g_attn[k, m]
// ---------------------------------------------------------------------------
__global__ __launch_bounds__(256) void mix_gemm(const float* __restrict__ image,
                                                const float* __restrict__ w,
                                                const float* __restrict__ bias,
                                                float* __restrict__ out) {
    __shared__ float As[32][64];
    __shared__ float Bs[32][64];
    const int bm = blockIdx.y * 64;
    const int bn = blockIdx.x * 64;
    const int tid = threadIdx.x;
    const int tx = tid & 15;
    const int ty = tid >> 4;
    const int n  = bm >> 10;
    const int t0 = bm & 1023;

    float acc[4][4] = {};
    float4* As4 = (float4*)&As[0][0];
    float4* Bs4 = (float4*)&Bs[0][0];

    for (int k0 = 0; k0 < 256; k0 += 32) {
        #pragma unroll
        for (int l = 0; l < 2; l++) {
            int idx = l * 256 + tid;
            int kk = idx >> 4, f4 = idx & 15;
            As4[idx] = *(const float4*)&g_attn[(size_t)(k0 + kk) * 8192 + bm + f4 * 4];
            Bs4[idx] = *(const float4*)&w[(k0 + kk) * 256 + bn + f4 * 4];
        }
        __syncthreads();
        #pragma unroll
        for (int kk = 0; kk < 32; kk++) {
            float4 a = *(const float4*)&As[kk][tx * 4];
            float4 b = *(const float4*)&Bs[kk][ty * 4];
            acc[0][0] += a.x * b.x; acc[0][1] += a.x * b.y; acc[0][2] += a.x * b.z; acc[0][3] += a.x * b.w;
            acc[1][0] += a.y * b.x; acc[1][1] += a.y * b.y; acc[1][2] += a.y * b.z; acc[1][3] += a.y * b.w;
            acc[2][0] += a.z * b.x; acc[2][1] += a.z * b.y; acc[2][2] += a.z * b.z; acc[2][3] += a.z * b.w;
            acc[3][0] += a.w * b.x; acc[3][1] += a.w * b.y; acc[3][2] += a.w * b.z; acc[3][3] += a.w * b.w;
        }
        __syncthreads();
    }

    #pragma unroll
    for (int j = 0; j < 4; j++) {
        const int o = bn + ty * 4 + j;
        const float bo = bias[o];
        const size_t gbase = (size_t)n * 262144 + (size_t)o * 1024 + t0 + tx * 4;
        float4 img = *(const float4*)&image[gbase];
        float4 v = make_float4(acc[0][j] + bo + img.x, acc[1][j] + bo + img.y,
                               acc[2][j] + bo + img.z, acc[3][j] + bo + img.w);
        *(float4*)&out[gbase] = v;
    }
}

// ---------------------------------------------------------------------------
extern "C" void kernel_launch(void* const* d_in, const int* in_sizes, int n_in,
                              void* d_out, int out_size) {
    const float* image = (const float*)d_in[0];
    const float* w_kqv = (const float*)d_in[1];
    const float* b_kqv = (const float*)d_in[2];
    const float* w_mix = (const float*)d_in[3];
    const float* b_mix = (const float*)d_in[4];
    float* out = (float*)d_out;

    dim3 gridA(768 / 64, 8192 / 64);
    kqv_gemm<<<gridA, 256>>>(image, w_kqv, b_kqv);

    dim3 gridB(8, 64);
    attn_kernel<<<gridB, 128>>>();

    dim3 gridC(256 / 64, 8192 / 64);
    mix_gemm<<<gridC, 256>>>(image, w_mix, b_mix, out);
}